// round 6
// baseline (speedup 1.0000x reference)
#include <cuda_runtime.h>

// Model_69080253989304 — 1-layer tanh RNN, SEQ=4096, BATCH=8192, HID=4.
// R5: software-pipeline the input projection c_t = W_ih*x_t + (b_ih+b_hh).
// In R3 the LDS of x (lat 29) + c FMA sat on the serial dependency chain
// (c is the innermost addend). Now c for step i+1 is computed during step i,
// which has ~44 cycles of slack -> steady-state chain is pure:
//   tanh stagger (3x8) + MUFU lat 16 + 1 FMA = ~44 cyc/step.
// One thread per batch chain; 128 CTAs x 64 thr -> 1 warp/SMSP on 128 SMs.

#define SEQ    4096
#define BATCH  8192
#define CHUNK  32
#define NCHUNK (SEQ / CHUNK)

__device__ __forceinline__ float tanh_fast(float x) {
    float r;
    asm("tanh.approx.f32 %0, %1;" : "=f"(r) : "f"(x));
    return r;
}

__global__ void __launch_bounds__(64, 1) rnn_scan_kernel(
    const float* __restrict__ x,      // (SEQ, BATCH, 1)
    const float* __restrict__ h0,     // (1, BATCH, HID)
    const float* __restrict__ W_ih,   // (HID, 1)
    const float* __restrict__ b_ih,   // (HID,)
    const float* __restrict__ W_hh,   // (HID, HID) row-major
    const float* __restrict__ b_hh,   // (HID,)
    const float* __restrict__ fc_W,   // (1, HID)
    const float* __restrict__ fc_b,   // (1,)
    float* __restrict__ out)          // [BATCH] y_last ++ [BATCH*HID] hn
{
    __shared__ float xb[2][CHUNK * 64];   // 16 KB, per-thread-private columns

    const int tid = threadIdx.x;
    const int b   = blockIdx.x * 64 + tid;

    // ---- broadcast weights into registers ----
    const float w00 = W_hh[0],  w01 = W_hh[1],  w02 = W_hh[2],  w03 = W_hh[3];
    const float w10 = W_hh[4],  w11 = W_hh[5],  w12 = W_hh[6],  w13 = W_hh[7];
    const float w20 = W_hh[8],  w21 = W_hh[9],  w22 = W_hh[10], w23 = W_hh[11];
    const float w30 = W_hh[12], w31 = W_hh[13], w32 = W_hh[14], w33 = W_hh[15];

    const float wi0 = W_ih[0], wi1 = W_ih[1], wi2 = W_ih[2], wi3 = W_ih[3];
    const float c0b = b_ih[0] + b_hh[0];
    const float c1b = b_ih[1] + b_hh[1];
    const float c2b = b_ih[2] + b_hh[2];
    const float c3b = b_ih[3] + b_hh[3];

    // ---- prologue: prefetch chunk 0 into buffer 0 via cp.async ----
    {
        const float* src = x + b;
        unsigned dst = (unsigned)__cvta_generic_to_shared(&xb[0][tid]);
#pragma unroll
        for (int i = 0; i < CHUNK; ++i) {
            asm volatile("cp.async.ca.shared.global [%0], [%1], 4;"
                         :: "r"(dst + i * 64 * 4), "l"(src + (size_t)i * BATCH)
                         : "memory");
        }
        asm volatile("cp.async.commit_group;" ::: "memory");
    }

    // ---- initial hidden state ----
    const float4 hi = reinterpret_cast<const float4*>(h0)[b];
    float hv0 = hi.x, hv1 = hi.y, hv2 = hi.z, hv3 = hi.w;

    for (int n = 0; n < NCHUNK; ++n) {
        // chunk n's loads are the only outstanding group -> wait for them
        asm volatile("cp.async.wait_group 0;" ::: "memory");

        const int cur = n & 1;
        const int nrow = (n + 1 < NCHUNK) ? (n + 1) * CHUNK : 0;
        const float* psrc = x + (size_t)nrow * BATCH + b;
        unsigned pdst = (unsigned)__cvta_generic_to_shared(&xb[cur ^ 1][tid]);
        const float* xcur = &xb[cur][tid];

        // peel: step 0's c computed here (only place LDS touches the chain,
        // once per 32 steps)
        float xv = xcur[0];
        float c0 = fmaf(wi0, xv, c0b);
        float c1 = fmaf(wi1, xv, c1b);
        float c2 = fmaf(wi2, xv, c2b);
        float c3 = fmaf(wi3, xv, c3b);

#pragma unroll
        for (int i = 0; i < CHUNK; ++i) {
            // prefetch x for step i+1 (independent of the chain; issued into
            // the chain's stall cycles). Last step's value is dead — the next
            // chunk's peel recomputes c after the wait.
            const float xn = (i + 1 < CHUNK) ? xcur[(i + 1) * 64] : 0.0f;

            // one cp.async per step spreads LDGSTS issue across the chunk
            asm volatile("cp.async.ca.shared.global [%0], [%1], 4;"
                         :: "r"(pdst + i * 64 * 4), "l"(psrc + (size_t)i * BATCH)
                         : "memory");

            // serial chain: c is ready (pipelined); consume hv in MUFU
            // arrival order (hv0 first)
            const float s0 = fmaf(w03, hv3, fmaf(w02, hv2, fmaf(w01, hv1, fmaf(w00, hv0, c0))));
            const float s1 = fmaf(w13, hv3, fmaf(w12, hv2, fmaf(w11, hv1, fmaf(w10, hv0, c1))));
            const float s2 = fmaf(w23, hv3, fmaf(w22, hv2, fmaf(w21, hv1, fmaf(w20, hv0, c2))));
            const float s3 = fmaf(w33, hv3, fmaf(w32, hv2, fmaf(w31, hv1, fmaf(w30, hv0, c3))));
            hv0 = tanh_fast(s0);
            hv1 = tanh_fast(s1);
            hv2 = tanh_fast(s2);
            hv3 = tanh_fast(s3);

            // compute c for step i+1 during this step's tanh latency
            c0 = fmaf(wi0, xn, c0b);
            c1 = fmaf(wi1, xn, c1b);
            c2 = fmaf(wi2, xn, c2b);
            c3 = fmaf(wi3, xn, c3b);
        }
        asm volatile("cp.async.commit_group;" ::: "memory");
    }

    // ---- epilogue: y = fc(h_T) ----
    const float y = fmaf(fc_W[3], hv3,
                    fmaf(fc_W[2], hv2,
                    fmaf(fc_W[1], hv1,
                    fmaf(fc_W[0], hv0, fc_b[0]))));

    out[b] = y;                                         // y_last: (BATCH, 1)
    float4 hvec;
    hvec.x = hv0; hvec.y = hv1; hvec.z = hv2; hvec.w = hv3;
    reinterpret_cast<float4*>(out + BATCH)[b] = hvec;   // hn: (1, BATCH, HID)
}

extern "C" void kernel_launch(void* const* d_in, const int* in_sizes, int n_in,
                              void* d_out, int out_size) {
    const float* x    = (const float*)d_in[0];
    const float* h0   = (const float*)d_in[1];
    const float* W_ih = (const float*)d_in[2];
    const float* b_ih = (const float*)d_in[3];
    const float* W_hh = (const float*)d_in[4];
    const float* b_hh = (const float*)d_in[5];
    const float* fc_W = (const float*)d_in[6];
    const float* fc_b = (const float*)d_in[7];
    float* out = (float*)d_out;

    rnn_scan_kernel<<<BATCH / 64, 64>>>(x, h0, W_ih, b_ih, W_hh, b_hh,
                                        fc_W, fc_b, out);
}

// round 12
// speedup vs baseline: 1.1091x; 1.1091x over previous
#include <cuda_runtime.h>

// Model_69080253989304 — 1-layer tanh RNN, SEQ=4096, BATCH=8192, HID=4.
// R10 = R6 re-bench (R6 run died to container infra, kernel never measured).
// R3 structure (best: 193us) + packed fma.rn.f32x2 arithmetic.
// With 1 warp/SMSP the FMA pipe (rt_SMSP=2) imposed a 20-FFMA x 2 = 40 cyc/step
// issue floor alongside the ~44-cyc dependency chain. Packing the (s0,s1) and
// (s2,s3) chains into f32x2 halves FMA instructions: 10 FFMA2 -> 20 cyc floor.
// h_j duplicated into {h_j,h_j} via ALU MOVs (ALU pipe idle at 1.7%).
// tanh remains scalar MUFU.TANH (numerics identical to R3: rel_err 1.1e-5).

#define SEQ    4096
#define BATCH  8192
#define CHUNK  32
#define NCHUNK (SEQ / CHUNK)

typedef unsigned long long u64;

__device__ __forceinline__ float tanh_fast(float x) {
    float r;
    asm("tanh.approx.f32 %0, %1;" : "=f"(r) : "f"(x));
    return r;
}
__device__ __forceinline__ u64 ffma2(u64 a, u64 b, u64 c) {
    u64 d;
    asm("fma.rn.f32x2 %0, %1, %2, %3;" : "=l"(d) : "l"(a), "l"(b), "l"(c));
    return d;
}
__device__ __forceinline__ u64 pack2(float lo, float hi) {
    u64 d;
    asm("mov.b64 %0, {%1, %2};" : "=l"(d) : "f"(lo), "f"(hi));
    return d;
}
__device__ __forceinline__ void unpack2(u64 v, float& lo, float& hi) {
    asm("mov.b64 {%0, %1}, %2;" : "=f"(lo), "=f"(hi) : "l"(v));
}

__global__ void __launch_bounds__(64, 1) rnn_scan_kernel(
    const float* __restrict__ x,      // (SEQ, BATCH, 1)
    const float* __restrict__ h0,     // (1, BATCH, HID)
    const float* __restrict__ W_ih,   // (HID, 1)
    const float* __restrict__ b_ih,   // (HID,)
    const float* __restrict__ W_hh,   // (HID, HID) row-major
    const float* __restrict__ b_hh,   // (HID,)
    const float* __restrict__ fc_W,   // (1, HID)
    const float* __restrict__ fc_b,   // (1,)
    float* __restrict__ out)          // [BATCH] y_last ++ [BATCH*HID] hn
{
    __shared__ float xb[2][CHUNK * 64];   // 16 KB, per-thread-private columns

    const int tid = threadIdx.x;
    const int b   = blockIdx.x * 64 + tid;

    // ---- packed weights: W01_j = {W_hh[0][j], W_hh[1][j]}, etc. ----
    const u64 W01_0 = pack2(W_hh[0],  W_hh[4]);
    const u64 W01_1 = pack2(W_hh[1],  W_hh[5]);
    const u64 W01_2 = pack2(W_hh[2],  W_hh[6]);
    const u64 W01_3 = pack2(W_hh[3],  W_hh[7]);
    const u64 W23_0 = pack2(W_hh[8],  W_hh[12]);
    const u64 W23_1 = pack2(W_hh[9],  W_hh[13]);
    const u64 W23_2 = pack2(W_hh[10], W_hh[14]);
    const u64 W23_3 = pack2(W_hh[11], W_hh[15]);

    const u64 wi01 = pack2(W_ih[0], W_ih[1]);
    const u64 wi23 = pack2(W_ih[2], W_ih[3]);
    const u64 cb01 = pack2(b_ih[0] + b_hh[0], b_ih[1] + b_hh[1]);
    const u64 cb23 = pack2(b_ih[2] + b_hh[2], b_ih[3] + b_hh[3]);

    // ---- prologue: prefetch chunk 0 into buffer 0 via cp.async ----
    {
        const float* src = x + b;
        unsigned dst = (unsigned)__cvta_generic_to_shared(&xb[0][tid]);
#pragma unroll
        for (int i = 0; i < CHUNK; ++i) {
            asm volatile("cp.async.ca.shared.global [%0], [%1], 4;"
                         :: "r"(dst + i * 64 * 4), "l"(src + (size_t)i * BATCH)
                         : "memory");
        }
        asm volatile("cp.async.commit_group;" ::: "memory");
    }

    // ---- initial hidden state ----
    const float4 hi = reinterpret_cast<const float4*>(h0)[b];
    float hv0 = hi.x, hv1 = hi.y, hv2 = hi.z, hv3 = hi.w;

    for (int n = 0; n < NCHUNK; ++n) {
        asm volatile("cp.async.wait_group 0;" ::: "memory");

        const int cur = n & 1;
        const int nrow = (n + 1 < NCHUNK) ? (n + 1) * CHUNK : 0;
        const float* psrc = x + (size_t)nrow * BATCH + b;
        unsigned pdst = (unsigned)__cvta_generic_to_shared(&xb[cur ^ 1][tid]);
        const float* xcur = &xb[cur][tid];

#pragma unroll
        for (int i = 0; i < CHUNK; ++i) {
            // one prefetch per step spreads LDGSTS issue across the chunk
            asm volatile("cp.async.ca.shared.global [%0], [%1], 4;"
                         :: "r"(pdst + i * 64 * 4), "l"(psrc + (size_t)i * BATCH)
                         : "memory");

            const float xv = xcur[i * 64];
            const u64 xx = pack2(xv, xv);
            // input projection (off the critical chain)
            const u64 c01 = ffma2(wi01, xx, cb01);
            const u64 c23 = ffma2(wi23, xx, cb23);

            // duplicate h components into pairs (ALU pipe, ~free)
            const u64 hh0 = pack2(hv0, hv0);
            const u64 hh1 = pack2(hv1, hv1);
            const u64 hh2 = pack2(hv2, hv2);
            const u64 hh3 = pack2(hv3, hv3);

            // two packed chains; consume h in MUFU arrival order (h0 first)
            const u64 s01 = ffma2(W01_3, hh3, ffma2(W01_2, hh2,
                            ffma2(W01_1, hh1, ffma2(W01_0, hh0, c01))));
            const u64 s23 = ffma2(W23_3, hh3, ffma2(W23_2, hh2,
                            ffma2(W23_1, hh1, ffma2(W23_0, hh0, c23))));

            float s0, s1, s2, s3;
            unpack2(s01, s0, s1);
            unpack2(s23, s2, s3);
            hv0 = tanh_fast(s0);
            hv1 = tanh_fast(s1);
            hv2 = tanh_fast(s2);
            hv3 = tanh_fast(s3);
        }
        asm volatile("cp.async.commit_group;" ::: "memory");
    }

    // ---- epilogue: y = fc(h_T) ----
    const float y = fmaf(fc_W[3], hv3,
                    fmaf(fc_W[2], hv2,
                    fmaf(fc_W[1], hv1,
                    fmaf(fc_W[0], hv0, fc_b[0]))));

    out[b] = y;                                         // y_last: (BATCH, 1)
    float4 hvec;
    hvec.x = hv0; hvec.y = hv1; hvec.z = hv2; hvec.w = hv3;
    reinterpret_cast<float4*>(out + BATCH)[b] = hvec;   // hn: (1, BATCH, HID)
}

extern "C" void kernel_launch(void* const* d_in, const int* in_sizes, int n_in,
                              void* d_out, int out_size) {
    const float* x    = (const float*)d_in[0];
    const float* h0   = (const float*)d_in[1];
    const float* W_ih = (const float*)d_in[2];
    const float* b_ih = (const float*)d_in[3];
    const float* W_hh = (const float*)d_in[4];
    const float* b_hh = (const float*)d_in[5];
    const float* fc_W = (const float*)d_in[6];
    const float* fc_b = (const float*)d_in[7];
    float* out = (float*)d_out;

    rnn_scan_kernel<<<BATCH / 64, 64>>>(x, h0, W_ih, b_ih, W_hh, b_hh,
                                        fc_W, fc_b, out);
}

// round 13
// speedup vs baseline: 1.4708x; 1.3261x over previous
#include <cuda_runtime.h>

// Model_69080253989304 — 1-layer tanh RNN, SEQ=4096, BATCH=8192, HID=4.
// R12: 4 threads per batch chain (lane j owns h_j). The 4 scalar tanh per step
// collapse into ONE warp-wide MUFU.TANH instruction, removing the 3*rt(16)=48
// cycle issue stagger that dominated the R10 period (86 cyc/step ~= 3*16+32+9).
// Cross-component h exchange via 3 SHFL.BFLY (lat 26, mutually overlapped),
// consumed in arrival order. New chain ~= tanh(32) + shfl(26..34) + 2 FMA(8)
// ~= 74 cyc. 32768 threads = 128 CTAs x 256 -> 2 warps/SMSP on 128 SMs;
// MUFU load drops 64 -> 16 cyc/step/warp-pair. fp32 throughout.

#define SEQ    4096
#define BATCH  8192
#define CHUNK  32
#define NCHUNK (SEQ / CHUNK)
#define CPC    64            // chains per CTA

__device__ __forceinline__ float tanh_fast(float x) {
    float r;
    asm("tanh.approx.f32 %0, %1;" : "=f"(r) : "f"(x));
    return r;
}

__global__ void __launch_bounds__(256, 1) rnn_scan_kernel(
    const float* __restrict__ x,      // (SEQ, BATCH, 1)
    const float* __restrict__ h0,     // (1, BATCH, HID)
    const float* __restrict__ W_ih,   // (HID, 1)
    const float* __restrict__ b_ih,   // (HID,)
    const float* __restrict__ W_hh,   // (HID, HID) row-major
    const float* __restrict__ b_hh,   // (HID,)
    const float* __restrict__ fc_W,   // (1, HID)
    const float* __restrict__ fc_b,   // (1,)
    float* __restrict__ out)          // [BATCH] y_last ++ [BATCH*HID] hn
{
    __shared__ float xb[2][CHUNK][CPC];   // 16 KB

    const int tid  = threadIdx.x;
    const int comp = tid & 3;             // which h component this lane owns
    const int cl   = tid >> 2;            // chain-local index 0..63
    const int b    = blockIdx.x * CPC + cl;

    // per-lane weight row of W_hh, ordered by shfl partner (bfly 1,2,3)
    const int r = comp * 4;
    const float wo = W_hh[r + comp];
    const float wa = W_hh[r + (comp ^ 1)];
    const float wb = W_hh[r + (comp ^ 2)];
    const float wc = W_hh[r + (comp ^ 3)];
    const float wi = W_ih[comp];
    const float cb = b_ih[comp] + b_hh[comp];

    float h = h0[(size_t)b * 4 + comp];

    const size_t gbase = (size_t)blockIdx.x * CPC;

    // ---- prologue: prefetch chunk 0 into buffer 0 (8 elems per thread) ----
#pragma unroll
    for (int k = 0; k < 8; ++k) {
        const int idx = k * 256 + tid;
        const int i   = idx >> 6;
        const int c   = idx & 63;
        unsigned dst = (unsigned)__cvta_generic_to_shared(&xb[0][i][c]);
        asm volatile("cp.async.ca.shared.global [%0], [%1], 4;"
                     :: "r"(dst), "l"(x + (size_t)i * BATCH + gbase + c)
                     : "memory");
    }
    asm volatile("cp.async.commit_group;" ::: "memory");

    for (int n = 0; n < NCHUNK; ++n) {
        asm volatile("cp.async.wait_group 0;" ::: "memory");
        __syncthreads();   // publish chunk n to all warps; fences prev reads

        const int cur  = n & 1;
        const int nrow = (n + 1 < NCHUNK) ? (n + 1) * CHUNK : 0;
        // issue prefetch of chunk n+1 before compute so it overlaps
#pragma unroll
        for (int k = 0; k < 8; ++k) {
            const int idx = k * 256 + tid;
            const int i   = idx >> 6;
            const int c   = idx & 63;
            unsigned dst = (unsigned)__cvta_generic_to_shared(&xb[cur ^ 1][i][c]);
            asm volatile("cp.async.ca.shared.global [%0], [%1], 4;"
                         :: "r"(dst), "l"(x + (size_t)(nrow + i) * BATCH + gbase + c)
                         : "memory");
        }
        asm volatile("cp.async.commit_group;" ::: "memory");

#pragma unroll
        for (int i = 0; i < CHUNK; ++i) {
            const float xv = xb[cur][i][cl];          // quad-broadcast LDS
            const float cc = fmaf(wi, xv, cb);        // off the critical chain
            // exchange h within the quad (3 overlapping SHFL.BFLY)
            const float ha = __shfl_xor_sync(0xffffffffu, h, 1);
            const float hb = __shfl_xor_sync(0xffffffffu, h, 2);
            const float hc = __shfl_xor_sync(0xffffffffu, h, 3);
            // consume own h first (ready at tanh-lat), shfl'd in arrival order
            const float s = fmaf(wc, hc,
                            fmaf(wb, hb,
                            fmaf(wa, ha,
                            fmaf(wo, h, cc))));
            h = tanh_fast(s);                         // ONE MUFU instr / step
        }
    }

    // ---- epilogue: y = fc(h_T) via quad reduction; hn scalar writes ----
    float p = fc_W[comp] * h;
    p += __shfl_xor_sync(0xffffffffu, p, 1);
    p += __shfl_xor_sync(0xffffffffu, p, 2);
    if (comp == 0) out[b] = p + fc_b[0];              // y_last: (BATCH, 1)
    out[(size_t)BATCH + (size_t)b * 4 + comp] = h;    // hn: (1, BATCH, HID)
}

extern "C" void kernel_launch(void* const* d_in, const int* in_sizes, int n_in,
                              void* d_out, int out_size) {
    const float* x    = (const float*)d_in[0];
    const float* h0   = (const float*)d_in[1];
    const float* W_ih = (const float*)d_in[2];
    const float* b_ih = (const float*)d_in[3];
    const float* W_hh = (const float*)d_in[4];
    const float* b_hh = (const float*)d_in[5];
    const float* fc_W = (const float*)d_in[6];
    const float* fc_b = (const float*)d_in[7];
    float* out = (float*)d_out;

    rnn_scan_kernel<<<(BATCH * 4) / 256, 256>>>(x, h0, W_ih, b_ih, W_hh, b_hh,
                                                fc_W, fc_b, out);
}